// round 8
// baseline (speedup 1.0000x reference)
#include <cuda_runtime.h>
#include <cuda_bf16.h>

// CLUB loss, single-pass formulation.
//   result = ( -0.5*P + 0.5/N * sum_d [ X2_d*S_d - 2*X_d*T_d ] ) / N
// with  P    = sum_{i,d} (x^2 - 2*x*mu) * exp(-lv)
//       X_d  = sum_i x,   X2_d = sum_i x^2
//       S_d  = sum_i exp(-lv),   T_d = sum_i mu*exp(-lv)
// (The mu^2 terms cancel between positive and negative.)
//
// Shapes: x (16,512,32,32) f32, p_mu (16384,512) f32, p_logvar (16384,512) f32.

#define NB   16
#define DD   512
#define HW   1024
#define NTOK (NB * HW)          // 16384
#define NSLICE 128
#define PITCH 129               // smem tile pitch (floats); 129 % 32 == 1

// Stateless per-launch scratch (fully overwritten each launch).
__device__ float gPart[4 * NSLICE * DD];   // [a][slice][d], 1 MB
__device__ float gP[1024];                 // per-block scalar partials
__device__ float gAccQ[4 * 4 * DD];        // [a][slice-quarter][d], 32 KB

__device__ __forceinline__ float4 ldcs4(const float* p) {
    return __ldcs(reinterpret_cast<const float4*>(p));
}

// Grid: 1024 blocks = 8 feature-chunks (64 each) x 128 token-slices (128 each).
__global__ __launch_bounds__(256) void club_main_kernel(
    const float* __restrict__ x,
    const float* __restrict__ pmu,
    const float* __restrict__ plv)
{
    __shared__ float xs[64 * PITCH];      // x tile: [feature][token], 33 KB
    __shared__ float red[4][8][64];       // cross-warp reduction buffer
    __shared__ float spc[8];

    const int tid  = threadIdx.x;
    const int w    = tid >> 5;
    const int lane = tid & 31;
    const int q    = lane & 15;           // float4 feature column (features q*4..q*4+3)
    const int th   = lane >> 4;           // token parity within pass
    const int bid  = blockIdx.x;

    const int dc    = (bid & 7) << 6;     // feature-chunk base (0..448)
    const int slice = bid >> 3;           // token-slice index  (0..127)
    const int i0    = slice << 7;         // first global token of slice
    const int b     = i0 >> 10;           // batch (slice never crosses batch)
    const int hw0   = i0 & 1023;
    const float* xb = x + ((size_t)((b << 9) + dc) << 10) + hw0;   // x[b, dc, hw0]

    // ---- stage x tile: 64 feature-rows x 128 tokens (32 float4 cols) ----
    // Warp covers 4 rows x 8 float4-cols -> conflict-free STS, 512B/row-chunk LDG.
    #pragma unroll
    for (int k = 0; k < 8; ++k) {
        const int qq  = tid + (k << 8);        // 0..2047
        const int c4l = qq & 7;
        const int row = (qq >> 3) & 63;
        const int c4h = qq >> 9;
        const int col = (c4h << 3) + c4l;      // float4 column 0..31
        float4 v = ldcs4(xb + (size_t)row * HW + (col << 2));
        float* d = &xs[row * PITCH + (col << 2)];
        d[0] = v.x; d[1] = v.y; d[2] = v.z; d[3] = v.w;
    }
    __syncthreads();

    // ---- main loop: warp w owns tokens [16w, 16w+16); pass p covers 2 tokens ----
    // Double-buffered prefetch (depth 2) on the mu/lv streams -> up to 4
    // independent 16B loads in flight per thread.
    float sX[4]  = {0.f, 0.f, 0.f, 0.f};
    float sXX[4] = {0.f, 0.f, 0.f, 0.f};
    float sS[4]  = {0.f, 0.f, 0.f, 0.f};
    float sT[4]  = {0.f, 0.f, 0.f, 0.f};
    float accP   = 0.f;

    const int tbase = (w << 4) + th;                       // first token of this thread
    const float* mp = pmu + (size_t)(i0 + tbase) * DD + dc + (q << 2);
    const float* lp = plv + (size_t)(i0 + tbase) * DD + dc + (q << 2);

    float4 mbuf[2], lbuf[2];
    mbuf[0] = ldcs4(mp);
    lbuf[0] = ldcs4(lp);
    mbuf[1] = ldcs4(mp + (size_t)(2 * DD));
    lbuf[1] = ldcs4(lp + (size_t)(2 * DD));

    #pragma unroll
    for (int p = 0; p < 8; ++p) {
        const int cur = p & 1;
        const float mm[4] = {mbuf[cur].x, mbuf[cur].y, mbuf[cur].z, mbuf[cur].w};
        const float ll[4] = {lbuf[cur].x, lbuf[cur].y, lbuf[cur].z, lbuf[cur].w};
        if (p < 6) {                                       // prefetch pass p+2
            mbuf[cur] = ldcs4(mp + (size_t)(2 * DD) * (p + 2));
            lbuf[cur] = ldcs4(lp + (size_t)(2 * DD) * (p + 2));
        }
        const int tl = tbase + (p << 1);
        const float* xrow = &xs[(q << 2) * PITCH + tl];
        float xv[4];
        xv[0] = xrow[0];
        xv[1] = xrow[PITCH];
        xv[2] = xrow[2 * PITCH];
        xv[3] = xrow[3 * PITCH];
        #pragma unroll
        for (int j = 0; j < 4; ++j) {
            const float iv = __expf(-ll[j]);
            const float xx = xv[j] * xv[j];
            const float e  = fmaf(xv[j] * mm[j], -2.0f, xx);   // x^2 - 2*x*mu
            accP   = fmaf(e, iv, accP);
            sS[j] += iv;
            sT[j]  = fmaf(mm[j], iv, sT[j]);
            sX[j] += xv[j];
            sXX[j] += xx;
        }
    }

    // ---- combine the two token-halves (lane ^ 16 holds same features) ----
    #pragma unroll
    for (int j = 0; j < 4; ++j) {
        sX[j]  += __shfl_xor_sync(0xffffffffu, sX[j],  16);
        sXX[j] += __shfl_xor_sync(0xffffffffu, sXX[j], 16);
        sS[j]  += __shfl_xor_sync(0xffffffffu, sS[j],  16);
        sT[j]  += __shfl_xor_sync(0xffffffffu, sT[j],  16);
    }
    #pragma unroll
    for (int o = 16; o; o >>= 1) accP += __shfl_xor_sync(0xffffffffu, accP, o);

    if (lane < 16) {
        #pragma unroll
        for (int j = 0; j < 4; ++j) {
            red[0][w][(q << 2) + j] = sX[j];
            red[1][w][(q << 2) + j] = sXX[j];
            red[2][w][(q << 2) + j] = sS[j];
            red[3][w][(q << 2) + j] = sT[j];
        }
    }
    if (lane == 0) spc[w] = accP;
    __syncthreads();

    {
        const int a  = tid >> 6;      // accumulator 0..3
        const int dd = tid & 63;      // feature within chunk
        float s = 0.f;
        #pragma unroll
        for (int ww = 0; ww < 8; ++ww) s += red[a][ww][dd];
        gPart[(a * NSLICE + slice) * DD + dc + dd] = s;   // coalesced
    }
    if (tid == 0) {
        float s = 0.f;
        #pragma unroll
        for (int ww = 0; ww < 8; ++ww) s += spc[ww];
        gP[bid] = s;
    }
}

// Stage 2: 64 blocks x 128 threads. Block b: a = b>>4, slice-quarter sq=(b>>2)&3,
// d-range dr = b&3. Each thread sums 32 slices for one d with 4 independent
// fp32 accumulators, loads coalesced across threads.
__global__ __launch_bounds__(128) void club_reduce_kernel()
{
    const int tid = threadIdx.x;
    const int b   = blockIdx.x;
    const int a   = b >> 4;
    const int sq  = (b >> 2) & 3;
    const int dr  = b & 3;
    const int d   = (dr << 7) + tid;

    const float* p = &gPart[((a * NSLICE) + (sq << 5)) * DD + d];
    float a0 = 0.f, a1 = 0.f, a2 = 0.f, a3 = 0.f;
    #pragma unroll
    for (int k = 0; k < 8; ++k) {
        const float* pk = p + (size_t)(k << 2) * DD;
        a0 += pk[0];
        a1 += pk[(size_t)DD];
        a2 += pk[(size_t)2 * DD];
        a3 += pk[(size_t)3 * DD];
    }
    gAccQ[((a << 2) + sq) * DD + d] = (a0 + a1) + (a2 + a3);
}

// Stage 3: tiny single-block finalize (reads 32 KB + 4 KB, all coalesced).
__global__ __launch_bounds__(512) void club_final_kernel(float* __restrict__ out)
{
    __shared__ double sd[512];
    __shared__ double sp[512];
    const int tid = threadIdx.x;   // tid == feature d

    double A[4];
    #pragma unroll
    for (int aa = 0; aa < 4; ++aa) {
        A[aa] = (double)gAccQ[((aa << 2) + 0) * DD + tid]
              + (double)gAccQ[((aa << 2) + 1) * DD + tid]
              + (double)gAccQ[((aa << 2) + 2) * DD + tid]
              + (double)gAccQ[((aa << 2) + 3) * DD + tid];
    }
    const double X = A[0], XX = A[1], S = A[2], T = A[3];

    sd[tid] = XX * S - 2.0 * X * T;
    sp[tid] = (double)gP[tid] + (double)gP[tid + 512];
    __syncthreads();

    #pragma unroll
    for (int o = 256; o; o >>= 1) {
        if (tid < o) { sd[tid] += sd[tid + o]; sp[tid] += sp[tid + o]; }
        __syncthreads();
    }
    if (tid == 0) {
        const double N = (double)NTOK;
        out[0] = (float)((-0.5 * sp[0] + 0.5 * sd[0] / N) / N);
    }
}

extern "C" void kernel_launch(void* const* d_in, const int* in_sizes, int n_in,
                              void* d_out, int out_size)
{
    const float* x   = (const float*)d_in[0];
    const float* pmu = (const float*)d_in[1];
    const float* plv = (const float*)d_in[2];
    float* out = (float*)d_out;

    club_main_kernel<<<1024, 256>>>(x, pmu, plv);
    club_reduce_kernel<<<64, 128>>>();
    club_final_kernel<<<1, 512>>>(out);
}

// round 10
// speedup vs baseline: 1.0012x; 1.0012x over previous
#include <cuda_runtime.h>
#include <cuda_bf16.h>
#include <cstdint>

// CLUB loss, single-pass formulation.
//   result = ( -0.5*P + 0.5/N * sum_d [ X2_d*S_d - 2*X_d*T_d ] ) / N
// with  P    = sum_{i,d} (x^2 - 2*x*mu) * exp(-lv)
//       X_d  = sum_i x,   X2_d = sum_i x^2
//       S_d  = sum_i exp(-lv),   T_d = sum_i mu*exp(-lv)
// (The mu^2 terms cancel between positive and negative.)
//
// Shapes: x (16,512,32,32) f32, p_mu (16384,512) f32, p_logvar (16384,512) f32.
//
// Main kernel: cp.async-staged streaming. Block = 64 features x 32 tokens,
// 24 KB staged per block, ~26 KB smem -> 8 blocks/SM -> ~192 KB in flight/SM.

#define DD   512
#define HW   1024
#define NTOK 16384
#define NSLICE 512              // 512 slices of 32 tokens
#define XPITCH 36               // x tile pitch (floats): 144B rows, 16B-aligned,
                                // 36%32==4 -> LDS.128 reads are 4-phase clean

// Stateless per-launch scratch (fully overwritten each launch).
__device__ float gPart[4 * NSLICE * DD];   // [a][slice][d], 4 MB
__device__ float gP[4096];                 // per-block scalar partials
__device__ float gAccO[4 * 16 * DD];       // [a][slice-group][d], 128 KB

__device__ __forceinline__ void cp16(unsigned int dst, const float* src) {
    asm volatile("cp.async.cg.shared.global [%0], [%1], 16;" :: "r"(dst), "l"(src));
}

// Grid: 4096 blocks = 8 feature-chunks (64 each) x 512 token-slices (32 each).
__global__ __launch_bounds__(256) void club_main_kernel(
    const float* __restrict__ x,
    const float* __restrict__ pmu,
    const float* __restrict__ plv)
{
    __shared__ float xs[64 * XPITCH];   // x tile [feature][token], 9.2 KB
    __shared__ float mus[32 * 64];      // mu tile [token][feature], 8 KB
    __shared__ float lvs[32 * 64];      // lv tile [token][feature], 8 KB
    __shared__ float red[4 * 4 * 64];   // [acc][tseg][feature]
    __shared__ float spc[8];

    const int tid = threadIdx.x;
    const int bid = blockIdx.x;
    const int dc    = (bid & 7) << 6;   // feature-chunk base (0..448)
    const int slice = bid >> 3;         // token-slice index  (0..511)
    const int i0    = slice << 5;       // first global token (slice never crosses batch)
    const int b     = i0 >> 10;
    const int hw0   = i0 & 1023;
    const float* xb = x + ((size_t)((b << 9) + dc) << 10) + hw0;   // x[b, dc, hw0]

    const unsigned int xs_a = (unsigned int)__cvta_generic_to_shared(xs);
    const unsigned int mu_a = (unsigned int)__cvta_generic_to_shared(mus);
    const unsigned int lv_a = (unsigned int)__cvta_generic_to_shared(lvs);

    // ---- stage x: 64 rows x 128B (8 x 16B chunks/row); warp = 4 rows x 128B ----
    #pragma unroll
    for (int k = 0; k < 2; ++k) {
        const int q   = tid + (k << 8);     // 0..511
        const int row = q >> 3;
        const int c4  = q & 7;
        cp16(xs_a + (unsigned int)(row * XPITCH + (c4 << 2)) * 4u,
             xb + (size_t)row * HW + (c4 << 2));
    }
    // ---- stage mu/lv: 32 tokens x 256B (16 chunks/token); warp = 2 tokens x 256B ----
    #pragma unroll
    for (int k = 0; k < 2; ++k) {
        const int q  = tid + (k << 8);      // 0..511
        const int t  = q >> 4;
        const int c4 = q & 15;
        const size_t off = (size_t)(i0 + t) * DD + dc + (c4 << 2);
        const unsigned int so = (unsigned int)((t << 6) + (c4 << 2)) * 4u;
        cp16(mu_a + so, pmu + off);
        cp16(lv_a + so, plv + off);
    }
    asm volatile("cp.async.commit_group;");
    asm volatile("cp.async.wait_group 0;" ::: "memory");
    __syncthreads();

    // ---- compute: thread owns feature f = tid&63, tokens [8*tseg, 8*tseg+8) ----
    const int f    = tid & 63;
    const int tseg = tid >> 6;
    const int t0   = tseg << 3;

    float sX = 0.f, sXX = 0.f, sS = 0.f, sT = 0.f, accP = 0.f;
    const float* xrow = xs + f * XPITCH + t0;

    #pragma unroll
    for (int j = 0; j < 2; ++j) {
        const float4 xq = *reinterpret_cast<const float4*>(xrow + (j << 2));
        const float xv[4] = {xq.x, xq.y, xq.z, xq.w};
        #pragma unroll
        for (int e = 0; e < 4; ++e) {
            const int t = t0 + (j << 2) + e;
            const float mu = mus[(t << 6) + f];     // bank f -> conflict-free
            const float lv = lvs[(t << 6) + f];
            const float iv = __expf(-lv);
            const float xx = xv[e] * xv[e];
            const float er = fmaf(xv[e] * mu, -2.0f, xx);   // x^2 - 2*x*mu
            accP = fmaf(er, iv, accP);
            sS  += iv;
            sT   = fmaf(mu, iv, sT);
            sX  += xv[e];
            sXX += xx;
        }
    }

    // ---- epilogue: reduce over the 4 token-segments per feature ----
    red[(0 * 4 + tseg) * 64 + f] = sX;
    red[(1 * 4 + tseg) * 64 + f] = sXX;
    red[(2 * 4 + tseg) * 64 + f] = sS;
    red[(3 * 4 + tseg) * 64 + f] = sT;

    #pragma unroll
    for (int o = 16; o; o >>= 1) accP += __shfl_xor_sync(0xffffffffu, accP, o);
    if ((tid & 31) == 0) spc[tid >> 5] = accP;
    __syncthreads();

    {
        const int a  = tid >> 6;      // accumulator 0..3
        const int ff = tid & 63;
        const float s = red[(a * 4 + 0) * 64 + ff] + red[(a * 4 + 1) * 64 + ff]
                      + red[(a * 4 + 2) * 64 + ff] + red[(a * 4 + 3) * 64 + ff];
        gPart[(a * NSLICE + slice) * DD + dc + ff] = s;   // coalesced
    }
    if (tid == 0) {
        float s = 0.f;
        #pragma unroll
        for (int ww = 0; ww < 8; ++ww) s += spc[ww];
        gP[bid] = s;
    }
}

// Stage 2: 256 blocks x 128 threads. Block b: a = b>>6, slice-group sg=(b>>2)&15,
// d-range dr = b&3. Each thread sums 32 slices for one d with 4 independent
// fp32 accumulators, loads coalesced across threads.
__global__ __launch_bounds__(128) void club_reduce_kernel()
{
    const int tid = threadIdx.x;
    const int bb  = blockIdx.x;
    const int a   = bb >> 6;
    const int sg  = (bb >> 2) & 15;
    const int dr  = bb & 3;
    const int d   = (dr << 7) + tid;

    const float* p = &gPart[((a * NSLICE) + (sg << 5)) * DD + d];
    float a0 = 0.f, a1 = 0.f, a2 = 0.f, a3 = 0.f;
    #pragma unroll
    for (int k = 0; k < 8; ++k) {
        const float* pk = p + (size_t)(k << 2) * DD;
        a0 += pk[0];
        a1 += pk[(size_t)DD];
        a2 += pk[(size_t)2 * DD];
        a3 += pk[(size_t)3 * DD];
    }
    gAccO[((a << 4) + sg) * DD + d] = (a0 + a1) + (a2 + a3);
}

// Stage 3: tiny single-block finalize (reads 128 KB + 16 KB, all coalesced).
__global__ __launch_bounds__(512) void club_final_kernel(float* __restrict__ out)
{
    __shared__ double sd[512];
    __shared__ double sp[512];
    const int tid = threadIdx.x;   // tid == feature d

    double A[4];
    #pragma unroll
    for (int aa = 0; aa < 4; ++aa) {
        double s0 = 0.0, s1 = 0.0;
        #pragma unroll
        for (int o = 0; o < 16; o += 2) {
            s0 += (double)gAccO[((aa << 4) + o) * DD + tid];
            s1 += (double)gAccO[((aa << 4) + o + 1) * DD + tid];
        }
        A[aa] = s0 + s1;
    }
    double pp = 0.0;
    #pragma unroll
    for (int k = 0; k < 8; ++k) pp += (double)gP[tid + (k << 9)];

    sd[tid] = A[1] * A[2] - 2.0 * A[0] * A[3];   // XX*S - 2*X*T
    sp[tid] = pp;
    __syncthreads();

    #pragma unroll
    for (int o = 256; o; o >>= 1) {
        if (tid < o) { sd[tid] += sd[tid + o]; sp[tid] += sp[tid + o]; }
        __syncthreads();
    }
    if (tid == 0) {
        const double N = (double)NTOK;
        out[0] = (float)((-0.5 * sp[0] + 0.5 * sd[0] / N) / N);
    }
}

extern "C" void kernel_launch(void* const* d_in, const int* in_sizes, int n_in,
                              void* d_out, int out_size)
{
    const float* x   = (const float*)d_in[0];
    const float* pmu = (const float*)d_in[1];
    const float* plv = (const float*)d_in[2];
    float* out = (float*)d_out;

    club_main_kernel<<<4096, 256>>>(x, pmu, plv);
    club_reduce_kernel<<<256, 128>>>();
    club_final_kernel<<<1, 512>>>(out);
}

// round 12
// speedup vs baseline: 1.2915x; 1.2899x over previous
#include <cuda_runtime.h>
#include <cuda_bf16.h>
#include <cstdint>

// CLUB loss, single-pass formulation.
//   result = ( -0.5*P + 0.5/N * sum_d [ X2_d*S_d - 2*X_d*T_d ] ) / N
// with  P    = sum_{i,d} (x^2 - 2*x*mu) * exp(-lv)
//       X_d  = sum_i x,   X2_d = sum_i x^2
//       S_d  = sum_i exp(-lv),   T_d = sum_i mu*exp(-lv)
// (The mu^2 terms cancel between positive and negative.)
//
// Shapes: x (16,512,32,32) f32, p_mu (16384,512) f32, p_logvar (16384,512) f32.
//
// Main kernel: pipelined cp.async streaming. Block = 64 features x 128 tokens,
// 4 sub-tiles of 32 tokens, 2-stage double buffer (24 KB/stage), dynamic smem.

#define DD   512
#define HW   1024
#define NTOK 16384
#define NSLICE 128              // 128 slices of 128 tokens
#define XPITCH 36               // x sub-tile pitch (floats); 16B-aligned, 4-phase clean

// Dynamic smem layout (floats):
//   xs[2][64*XPITCH]  : 2 * 2304
//   mus[2][32*64]     : 2 * 2048
//   lvs[2][32*64]     : 2 * 2048
//   red[4*4*64]       : 1024
//   spc[8]            : 8
#define XS_FLOATS   (64 * XPITCH)
#define MU_FLOATS   (32 * 64)
#define SMEM_FLOATS (2 * XS_FLOATS + 4 * MU_FLOATS + 1024 + 8)
#define SMEM_BYTES  (SMEM_FLOATS * 4)

// Stateless per-launch scratch (fully overwritten each launch).
__device__ float gPart[4 * NSLICE * DD];   // [a][slice][d], 1 MB
__device__ float gP[1024];                 // per-block scalar partials
__device__ float gAccQ[4 * 4 * DD];        // [a][slice-quarter][d], 32 KB

__device__ __forceinline__ void cp16(unsigned int dst, const float* src) {
    asm volatile("cp.async.cg.shared.global [%0], [%1], 16;" :: "r"(dst), "l"(src));
}

// Grid: 1024 blocks = 8 feature-chunks (64 each) x 128 token-slices (128 each).
__global__ __launch_bounds__(256) void club_main_kernel(
    const float* __restrict__ x,
    const float* __restrict__ pmu,
    const float* __restrict__ plv)
{
    extern __shared__ float smem[];
    float* xsb[2];  xsb[0] = smem;                 xsb[1] = smem + XS_FLOATS;
    float* musb[2]; musb[0] = smem + 2 * XS_FLOATS;            musb[1] = musb[0] + MU_FLOATS;
    float* lvsb[2]; lvsb[0] = musb[1] + MU_FLOATS;             lvsb[1] = lvsb[0] + MU_FLOATS;
    float* red = lvsb[1] + MU_FLOATS;              // [acc][tseg][feature], 1024 floats
    float* spc = red + 1024;

    const int tid = threadIdx.x;
    const int bid = blockIdx.x;
    const int dc    = (bid & 7) << 6;   // feature-chunk base (0..448)
    const int slice = bid >> 3;         // token-slice index  (0..127)
    const int i0    = slice << 7;       // first global token (slice never crosses batch)
    const int b     = i0 >> 10;
    const int hw0   = i0 & 1023;
    const float* xb = x + ((size_t)((b << 9) + dc) << 10) + hw0;   // x[b, dc, hw0]

    // Per-thread staging coordinates (same for every sub-tile).
    const int xrow0 = tid >> 3;                 // 0..31  (row for k=0)
    const int xc4   = tid & 7;                  // x 16B chunk within row
    const int mt    = tid >> 4;                 // 0..15  (token for k=0)
    const int mc4   = tid & 15;                 // mu/lv 16B chunk within token

    unsigned int xs_a[2], mu_a[2], lv_a[2];
    #pragma unroll
    for (int bi = 0; bi < 2; ++bi) {
        xs_a[bi] = (unsigned int)__cvta_generic_to_shared(xsb[bi]);
        mu_a[bi] = (unsigned int)__cvta_generic_to_shared(musb[bi]);
        lv_a[bi] = (unsigned int)__cvta_generic_to_shared(lvsb[bi]);
    }

    // Stage sub-tile s (tokens [32s, 32s+32)) into buffer bi.
    auto stage = [&](int s, int bi) {
        const int toff = s << 5;
        #pragma unroll
        for (int k = 0; k < 2; ++k) {
            const int row = xrow0 + (k << 5);
            cp16(xs_a[bi] + (unsigned int)(row * XPITCH + (xc4 << 2)) * 4u,
                 xb + (size_t)row * HW + toff + (xc4 << 2));
        }
        #pragma unroll
        for (int k = 0; k < 2; ++k) {
            const int t = mt + (k << 4);
            const size_t off = (size_t)(i0 + toff + t) * DD + dc + (mc4 << 2);
            const unsigned int so = (unsigned int)((t << 6) + (mc4 << 2)) * 4u;
            cp16(mu_a[bi] + so, pmu + off);
            cp16(lv_a[bi] + so, plv + off);
        }
        asm volatile("cp.async.commit_group;");
    };

    stage(0, 0);
    stage(1, 1);

    // ---- compute: thread owns feature f = tid&63, tokens [8*tseg, 8*tseg+8)
    //      within each 32-token sub-tile ----
    const int f    = tid & 63;
    const int tseg = tid >> 6;
    const int t0   = tseg << 3;

    float sX = 0.f, sXX = 0.f, sS = 0.f, sT = 0.f, accP = 0.f;

    #pragma unroll
    for (int s = 0; s < 4; ++s) {
        const int bi = s & 1;
        if (s < 3) { asm volatile("cp.async.wait_group 1;" ::: "memory"); }
        else       { asm volatile("cp.async.wait_group 0;" ::: "memory"); }
        __syncthreads();

        const float* xrow = xsb[bi] + f * XPITCH + t0;
        const float* mrow = musb[bi];
        const float* lrow = lvsb[bi];
        #pragma unroll
        for (int j = 0; j < 2; ++j) {
            const float4 xq = *reinterpret_cast<const float4*>(xrow + (j << 2));
            const float xv[4] = {xq.x, xq.y, xq.z, xq.w};
            #pragma unroll
            for (int e = 0; e < 4; ++e) {
                const int t = t0 + (j << 2) + e;
                const float mu = mrow[(t << 6) + f];   // conflict-free
                const float lv = lrow[(t << 6) + f];
                const float iv = __expf(-lv);
                const float xx = xv[e] * xv[e];
                const float er = fmaf(xv[e] * mu, -2.0f, xx);   // x^2 - 2*x*mu
                accP = fmaf(er, iv, accP);
                sS  += iv;
                sT   = fmaf(mu, iv, sT);
                sX  += xv[e];
                sXX += xx;
            }
        }
        __syncthreads();                   // everyone done with buffer bi
        if (s + 2 < 4) stage(s + 2, bi);   // refill the freed buffer
    }

    // ---- epilogue: reduce over the 4 token-segments per feature ----
    red[(0 * 4 + tseg) * 64 + f] = sX;
    red[(1 * 4 + tseg) * 64 + f] = sXX;
    red[(2 * 4 + tseg) * 64 + f] = sS;
    red[(3 * 4 + tseg) * 64 + f] = sT;

    #pragma unroll
    for (int o = 16; o; o >>= 1) accP += __shfl_xor_sync(0xffffffffu, accP, o);
    if ((tid & 31) == 0) spc[tid >> 5] = accP;
    __syncthreads();

    {
        const int a  = tid >> 6;      // accumulator 0..3
        const int ff = tid & 63;
        const float s = red[(a * 4 + 0) * 64 + ff] + red[(a * 4 + 1) * 64 + ff]
                      + red[(a * 4 + 2) * 64 + ff] + red[(a * 4 + 3) * 64 + ff];
        gPart[(a * NSLICE + slice) * DD + dc + ff] = s;   // coalesced
    }
    if (tid == 0) {
        float s = 0.f;
        #pragma unroll
        for (int ww = 0; ww < 8; ++ww) s += spc[ww];
        gP[bid] = s;
    }
}

// Stage 2: 64 blocks x 128 threads. Block b: a = b>>4, slice-quarter sq=(b>>2)&3,
// d-range dr = b&3. Each thread sums 32 slices for one d with 4 independent
// fp32 accumulators, loads coalesced across threads.
__global__ __launch_bounds__(128) void club_reduce_kernel()
{
    const int tid = threadIdx.x;
    const int bb  = blockIdx.x;
    const int a   = bb >> 4;
    const int sq  = (bb >> 2) & 3;
    const int dr  = bb & 3;
    const int d   = (dr << 7) + tid;

    const float* p = &gPart[((a * NSLICE) + (sq << 5)) * DD + d];
    float a0 = 0.f, a1 = 0.f, a2 = 0.f, a3 = 0.f;
    #pragma unroll
    for (int k = 0; k < 8; ++k) {
        const float* pk = p + (size_t)(k << 2) * DD;
        a0 += pk[0];
        a1 += pk[(size_t)DD];
        a2 += pk[(size_t)2 * DD];
        a3 += pk[(size_t)3 * DD];
    }
    gAccQ[((a << 2) + sq) * DD + d] = (a0 + a1) + (a2 + a3);
}

// Stage 3: tiny single-block finalize (reads 32 KB + 4 KB, all coalesced).
__global__ __launch_bounds__(512) void club_final_kernel(float* __restrict__ out)
{
    __shared__ double sd[512];
    __shared__ double sp[512];
    const int tid = threadIdx.x;   // tid == feature d

    double A[4];
    #pragma unroll
    for (int aa = 0; aa < 4; ++aa) {
        A[aa] = (double)gAccQ[((aa << 2) + 0) * DD + tid]
              + (double)gAccQ[((aa << 2) + 1) * DD + tid]
              + (double)gAccQ[((aa << 2) + 2) * DD + tid]
              + (double)gAccQ[((aa << 2) + 3) * DD + tid];
    }
    double pp = (double)gP[tid] + (double)gP[tid + 512];

    sd[tid] = A[1] * A[2] - 2.0 * A[0] * A[3];   // XX*S - 2*X*T
    sp[tid] = pp;
    __syncthreads();

    #pragma unroll
    for (int o = 256; o; o >>= 1) {
        if (tid < o) { sd[tid] += sd[tid + o]; sp[tid] += sp[tid + o]; }
        __syncthreads();
    }
    if (tid == 0) {
        const double N = (double)NTOK;
        out[0] = (float)((-0.5 * sp[0] + 0.5 * sd[0] / N) / N);
    }
}

extern "C" void kernel_launch(void* const* d_in, const int* in_sizes, int n_in,
                              void* d_out, int out_size)
{
    const float* x   = (const float*)d_in[0];
    const float* pmu = (const float*)d_in[1];
    const float* plv = (const float*)d_in[2];
    float* out = (float*)d_out;

    // Idempotent; attribute set (not an allocation), not a stream op.
    cudaFuncSetAttribute(club_main_kernel,
                         cudaFuncAttributeMaxDynamicSharedMemorySize, SMEM_BYTES);

    club_main_kernel<<<1024, 256, SMEM_BYTES>>>(x, pmu, plv);
    club_reduce_kernel<<<64, 128>>>();
    club_final_kernel<<<1, 512>>>(out);
}

// round 13
// speedup vs baseline: 1.4191x; 1.0988x over previous
#include <cuda_runtime.h>
#include <cuda_bf16.h>
#include <cstdint>

// CLUB loss, single-pass formulation.
//   result = ( -0.5*P + 0.5/N * sum_d [ X2_d*S_d - 2*X_d*T_d ] ) / N
// with  P    = sum_{i,d} (x^2 - 2*x*mu) * exp(-lv)
//       X_d  = sum_i x,   X2_d = sum_i x^2
//       S_d  = sum_i exp(-lv),   T_d = sum_i mu*exp(-lv)
// (The mu^2 terms cancel between positive and negative.)
//
// Shapes: x (16,512,32,32) f32, p_mu (16384,512) f32, p_logvar (16384,512) f32.
//
// Main kernel: pipelined cp.async streaming. Block = 64 features x 128 tokens,
// 8 sub-tiles of 16 tokens, 2-stage double buffer (12 KB/stage), ~28 KB smem
// -> 8 blocks/SM -> grid 1024 fits in ONE wave (capacity 1184).

#define DD   512
#define HW   1024
#define NTOK 16384
#define NSLICE 128              // 128 slices of 128 tokens

// Stateless per-launch scratch (fully overwritten each launch).
__device__ float gPart[4 * NSLICE * DD];   // [a][slice][d], 1 MB
__device__ float gP[1024];                 // per-block scalar partials
__device__ float gAccQ[4 * 4 * DD];        // [a][slice-quarter][d], 32 KB

__device__ __forceinline__ void cp16(unsigned int dst, const float* src) {
    asm volatile("cp.async.cg.shared.global [%0], [%1], 16;" :: "r"(dst), "l"(src));
}

// x tile: [feature][16 tokens], pitch 16 floats, XOR chunk swizzle
// c' = c ^ ((f>>1)&3). Guarantees each 8-lane LDS.128 phase covers 8 distinct
// 4-bank groups -> conflict-free on both store and load sides.
__device__ __forceinline__ int xword(int f, int c) {
    return (f << 4) + ((c ^ ((f >> 1) & 3)) << 2);
}

// Grid: 1024 blocks = 8 feature-chunks (64 each) x 128 token-slices (128 each).
__global__ __launch_bounds__(256) void club_main_kernel(
    const float* __restrict__ x,
    const float* __restrict__ pmu,
    const float* __restrict__ plv)
{
    __shared__ float xs[2][64 * 16];    // 2 x 4 KB
    __shared__ float mus[2][16 * 64];   // 2 x 4 KB
    __shared__ float lvs[2][16 * 64];   // 2 x 4 KB
    __shared__ float red[4 * 4 * 64];   // [acc][tseg][feature]
    __shared__ float spc[8];

    const int tid = threadIdx.x;
    const int bid = blockIdx.x;
    const int dc    = (bid & 7) << 6;   // feature-chunk base (0..448)
    const int slice = bid >> 3;         // token-slice index  (0..127)
    const int i0    = slice << 7;       // first global token (slice never crosses batch)
    const int b     = i0 >> 10;
    const int hw0   = i0 & 1023;
    const float* xb = x + ((size_t)((b << 9) + dc) << 10) + hw0;   // x[b, dc, hw0]

    // Per-thread staging coordinates (same for every sub-tile).
    const int xf  = tid >> 2;           // feature row 0..63
    const int xc  = tid & 3;            // 16B chunk within 64B row
    const int mt  = tid >> 4;           // token 0..15
    const int mc4 = tid & 15;           // 16B chunk within 256B token row

    unsigned int xs_a[2], mu_a[2], lv_a[2];
    #pragma unroll
    for (int bi = 0; bi < 2; ++bi) {
        xs_a[bi] = (unsigned int)__cvta_generic_to_shared(xs[bi]);
        mu_a[bi] = (unsigned int)__cvta_generic_to_shared(mus[bi]);
        lv_a[bi] = (unsigned int)__cvta_generic_to_shared(lvs[bi]);
    }

    // Stage sub-tile s (tokens [16s, 16s+16)) into buffer bi. 3 cp.async/thread.
    auto stage = [&](int s, int bi) {
        const int toff = s << 4;
        cp16(xs_a[bi] + (unsigned int)xword(xf, xc) * 4u,
             xb + (size_t)xf * HW + toff + (xc << 2));
        const size_t off = (size_t)(i0 + toff + mt) * DD + dc + (mc4 << 2);
        const unsigned int so = (unsigned int)((mt << 6) + (mc4 << 2)) * 4u;
        cp16(mu_a[bi] + so, pmu + off);
        cp16(lv_a[bi] + so, plv + off);
        asm volatile("cp.async.commit_group;");
    };

    stage(0, 0);
    stage(1, 1);

    // ---- compute: thread owns feature f = tid&63, tokens [4*tseg, 4*tseg+4)
    //      within each 16-token sub-tile ----
    const int f    = tid & 63;
    const int tseg = tid >> 6;
    const int t0   = tseg << 2;
    const int xw   = xword(f, tseg);    // swizzled float4 word for this thread

    float sX = 0.f, sXX = 0.f, sS = 0.f, sT = 0.f, accP = 0.f;

    #pragma unroll
    for (int s = 0; s < 8; ++s) {
        const int bi = s & 1;
        if (s < 7) { asm volatile("cp.async.wait_group 1;" ::: "memory"); }
        else       { asm volatile("cp.async.wait_group 0;" ::: "memory"); }
        __syncthreads();

        const float4 xq = *reinterpret_cast<const float4*>(&xs[bi][xw]);
        const float xv[4] = {xq.x, xq.y, xq.z, xq.w};
        const float* mrow = mus[bi];
        const float* lrow = lvs[bi];
        #pragma unroll
        for (int e = 0; e < 4; ++e) {
            const int t = t0 + e;
            const float mu = mrow[(t << 6) + f];   // conflict-free
            const float lv = lrow[(t << 6) + f];
            const float iv = __expf(-lv);
            const float xx = xv[e] * xv[e];
            const float er = fmaf(xv[e] * mu, -2.0f, xx);   // x^2 - 2*x*mu
            accP = fmaf(er, iv, accP);
            sS  += iv;
            sT   = fmaf(mu, iv, sT);
            sX  += xv[e];
            sXX += xx;
        }
        __syncthreads();                   // everyone done with buffer bi
        if (s + 2 < 8) stage(s + 2, bi);   // refill the freed buffer
    }

    // ---- epilogue: reduce over the 4 token-segments per feature ----
    red[(0 * 4 + tseg) * 64 + f] = sX;
    red[(1 * 4 + tseg) * 64 + f] = sXX;
    red[(2 * 4 + tseg) * 64 + f] = sS;
    red[(3 * 4 + tseg) * 64 + f] = sT;

    #pragma unroll
    for (int o = 16; o; o >>= 1) accP += __shfl_xor_sync(0xffffffffu, accP, o);
    if ((tid & 31) == 0) spc[tid >> 5] = accP;
    __syncthreads();

    {
        const int a  = tid >> 6;      // accumulator 0..3
        const int ff = tid & 63;
        const float s = red[(a * 4 + 0) * 64 + ff] + red[(a * 4 + 1) * 64 + ff]
                      + red[(a * 4 + 2) * 64 + ff] + red[(a * 4 + 3) * 64 + ff];
        gPart[(a * NSLICE + slice) * DD + dc + ff] = s;   // coalesced
    }
    if (tid == 0) {
        float s = 0.f;
        #pragma unroll
        for (int ww = 0; ww < 8; ++ww) s += spc[ww];
        gP[bid] = s;
    }
}

// Stage 2: 64 blocks x 128 threads. Block b: a = b>>4, slice-quarter sq=(b>>2)&3,
// d-range dr = b&3. Each thread sums 32 slices for one d with 4 independent
// fp32 accumulators, loads coalesced across threads.
__global__ __launch_bounds__(128) void club_reduce_kernel()
{
    const int tid = threadIdx.x;
    const int bb  = blockIdx.x;
    const int a   = bb >> 4;
    const int sq  = (bb >> 2) & 3;
    const int dr  = bb & 3;
    const int d   = (dr << 7) + tid;

    const float* p = &gPart[((a * NSLICE) + (sq << 5)) * DD + d];
    float a0 = 0.f, a1 = 0.f, a2 = 0.f, a3 = 0.f;
    #pragma unroll
    for (int k = 0; k < 8; ++k) {
        const float* pk = p + (size_t)(k << 2) * DD;
        a0 += pk[0];
        a1 += pk[(size_t)DD];
        a2 += pk[(size_t)2 * DD];
        a3 += pk[(size_t)3 * DD];
    }
    gAccQ[((a << 2) + sq) * DD + d] = (a0 + a1) + (a2 + a3);
}

// Stage 3: tiny single-block finalize (reads 32 KB + 4 KB, all coalesced).
__global__ __launch_bounds__(512) void club_final_kernel(float* __restrict__ out)
{
    __shared__ double sd[512];
    __shared__ double sp[512];
    const int tid = threadIdx.x;   // tid == feature d

    double A[4];
    #pragma unroll
    for (int aa = 0; aa < 4; ++aa) {
        A[aa] = (double)gAccQ[((aa << 2) + 0) * DD + tid]
              + (double)gAccQ[((aa << 2) + 1) * DD + tid]
              + (double)gAccQ[((aa << 2) + 2) * DD + tid]
              + (double)gAccQ[((aa << 2) + 3) * DD + tid];
    }
    double pp = (double)gP[tid] + (double)gP[tid + 512];

    sd[tid] = A[1] * A[2] - 2.0 * A[0] * A[3];   // XX*S - 2*X*T
    sp[tid] = pp;
    __syncthreads();

    #pragma unroll
    for (int o = 256; o; o >>= 1) {
        if (tid < o) { sd[tid] += sd[tid + o]; sp[tid] += sp[tid + o]; }
        __syncthreads();
    }
    if (tid == 0) {
        const double N = (double)NTOK;
        out[0] = (float)((-0.5 * sp[0] + 0.5 * sd[0] / N) / N);
    }
}

extern "C" void kernel_launch(void* const* d_in, const int* in_sizes, int n_in,
                              void* d_out, int out_size)
{
    const float* x   = (const float*)d_in[0];
    const float* pmu = (const float*)d_in[1];
    const float* plv = (const float*)d_in[2];
    float* out = (float*)d_out;

    club_main_kernel<<<1024, 256>>>(x, pmu, plv);
    club_reduce_kernel<<<64, 128>>>();
    club_final_kernel<<<1, 512>>>(out);
}

// round 14
// speedup vs baseline: 1.6112x; 1.1354x over previous
#include <cuda_runtime.h>
#include <cuda_bf16.h>
#include <cstdint>

// CLUB loss, single-pass formulation.
//   result = ( -0.5*P + 0.5/N * sum_d [ X2_d*S_d - 2*X_d*T_d ] ) / N
// with  P    = sum_{i,d} (x^2 - 2*x*mu) * exp(-lv)
//       X_d  = sum_i x,   X2_d = sum_i x^2
//       S_d  = sum_i exp(-lv),   T_d = sum_i mu*exp(-lv)
// (The mu^2 terms cancel between positive and negative.)
//
// Shapes: x (16,512,32,32) f32, p_mu (16384,512) f32, p_logvar (16384,512) f32.
//
// Main kernel (frozen from R13 best): pipelined cp.async streaming.
// Block = 64 features x 128 tokens, 8 sub-tiles of 16 tokens, 2-stage double
// buffer, ~28 KB smem -> 8 blocks/SM -> grid 1024 fits in ONE wave.
// Tail: per-d partials combined via atomicAdd (REDG) into gAcc; one tiny
// finalize kernel reads 12 KB, computes in double, re-zeroes gAcc.

#define DD   512
#define HW   1024
#define NTOK 16384

// Per-launch accumulators. Zero at load; finalize re-zeroes after consuming,
// so the zero-at-entry invariant holds across graph replays.
__device__ float gAcc[4 * DD];   // [a][d] atomic accumulation targets
__device__ float gP[1024];       // per-block scalar partials (overwritten)

__device__ __forceinline__ void cp16(unsigned int dst, const float* src) {
    asm volatile("cp.async.cg.shared.global [%0], [%1], 16;" :: "r"(dst), "l"(src));
}

// x tile: [feature][16 tokens], pitch 16 floats, XOR chunk swizzle
// c' = c ^ ((f>>1)&3) -> conflict-free LDS.128 on store and load sides.
__device__ __forceinline__ int xword(int f, int c) {
    return (f << 4) + ((c ^ ((f >> 1) & 3)) << 2);
}

// Grid: 1024 blocks = 8 feature-chunks (64 each) x 128 token-slices (128 each).
__global__ __launch_bounds__(256) void club_main_kernel(
    const float* __restrict__ x,
    const float* __restrict__ pmu,
    const float* __restrict__ plv)
{
    __shared__ float xs[2][64 * 16];    // 2 x 4 KB
    __shared__ float mus[2][16 * 64];   // 2 x 4 KB
    __shared__ float lvs[2][16 * 64];   // 2 x 4 KB
    __shared__ float red[4 * 4 * 64];   // [acc][tseg][feature]
    __shared__ float spc[8];

    const int tid = threadIdx.x;
    const int bid = blockIdx.x;
    const int dc    = (bid & 7) << 6;   // feature-chunk base (0..448)
    const int slice = bid >> 3;         // token-slice index  (0..127)
    const int i0    = slice << 7;       // first global token (slice never crosses batch)
    const int b     = i0 >> 10;
    const int hw0   = i0 & 1023;
    const float* xb = x + ((size_t)((b << 9) + dc) << 10) + hw0;   // x[b, dc, hw0]

    // Per-thread staging coordinates (same for every sub-tile).
    const int xf  = tid >> 2;           // feature row 0..63
    const int xc  = tid & 3;            // 16B chunk within 64B row
    const int mt  = tid >> 4;           // token 0..15
    const int mc4 = tid & 15;           // 16B chunk within 256B token row

    unsigned int xs_a[2], mu_a[2], lv_a[2];
    #pragma unroll
    for (int bi = 0; bi < 2; ++bi) {
        xs_a[bi] = (unsigned int)__cvta_generic_to_shared(xs[bi]);
        mu_a[bi] = (unsigned int)__cvta_generic_to_shared(mus[bi]);
        lv_a[bi] = (unsigned int)__cvta_generic_to_shared(lvs[bi]);
    }

    // Stage sub-tile s (tokens [16s, 16s+16)) into buffer bi. 3 cp.async/thread.
    auto stage = [&](int s, int bi) {
        const int toff = s << 4;
        cp16(xs_a[bi] + (unsigned int)xword(xf, xc) * 4u,
             xb + (size_t)xf * HW + toff + (xc << 2));
        const size_t off = (size_t)(i0 + toff + mt) * DD + dc + (mc4 << 2);
        const unsigned int so = (unsigned int)((mt << 6) + (mc4 << 2)) * 4u;
        cp16(mu_a[bi] + so, pmu + off);
        cp16(lv_a[bi] + so, plv + off);
        asm volatile("cp.async.commit_group;");
    };

    stage(0, 0);
    stage(1, 1);

    // ---- compute: thread owns feature f = tid&63, tokens [4*tseg, 4*tseg+4)
    //      within each 16-token sub-tile ----
    const int f    = tid & 63;
    const int tseg = tid >> 6;
    const int t0   = tseg << 2;
    const int xw   = xword(f, tseg);    // swizzled float4 word for this thread

    float sX = 0.f, sXX = 0.f, sS = 0.f, sT = 0.f, accP = 0.f;

    #pragma unroll
    for (int s = 0; s < 8; ++s) {
        const int bi = s & 1;
        if (s < 7) { asm volatile("cp.async.wait_group 1;" ::: "memory"); }
        else       { asm volatile("cp.async.wait_group 0;" ::: "memory"); }
        __syncthreads();

        const float4 xq = *reinterpret_cast<const float4*>(&xs[bi][xw]);
        const float xv[4] = {xq.x, xq.y, xq.z, xq.w};
        const float* mrow = mus[bi];
        const float* lrow = lvs[bi];
        #pragma unroll
        for (int e = 0; e < 4; ++e) {
            const int t = t0 + e;
            const float mu = mrow[(t << 6) + f];   // conflict-free
            const float lv = lrow[(t << 6) + f];
            const float iv = __expf(-lv);
            const float xx = xv[e] * xv[e];
            const float er = fmaf(xv[e] * mu, -2.0f, xx);   // x^2 - 2*x*mu
            accP = fmaf(er, iv, accP);
            sS  += iv;
            sT   = fmaf(mu, iv, sT);
            sX  += xv[e];
            sXX += xx;
        }
        if (s < 6) {                       // buffer bi will be refilled
            __syncthreads();               // everyone done with buffer bi
            stage(s + 2, bi);
        }
        // s == 6,7: no refill; epilogue's __syncthreads covers the hazard.
    }

    // ---- epilogue: reduce over the 4 token-segments per feature ----
    __syncthreads();
    red[(0 * 4 + tseg) * 64 + f] = sX;
    red[(1 * 4 + tseg) * 64 + f] = sXX;
    red[(2 * 4 + tseg) * 64 + f] = sS;
    red[(3 * 4 + tseg) * 64 + f] = sT;

    #pragma unroll
    for (int o = 16; o; o >>= 1) accP += __shfl_xor_sync(0xffffffffu, accP, o);
    if ((tid & 31) == 0) spc[tid >> 5] = accP;
    __syncthreads();

    {
        const int a  = tid >> 6;      // accumulator 0..3
        const int ff = tid & 63;
        const float s = red[(a * 4 + 0) * 64 + ff] + red[(a * 4 + 1) * 64 + ff]
                      + red[(a * 4 + 2) * 64 + ff] + red[(a * 4 + 3) * 64 + ff];
        atomicAdd(&gAcc[a * DD + dc + ff], s);   // REDG, 128 adds/address
    }
    if (tid == 0) {
        float s = 0.f;
        #pragma unroll
        for (int ww = 0; ww < 8; ++ww) s += spc[ww];
        gP[bid] = s;
    }
}

// Finalize: single block, reads 8 KB (gAcc) + 4 KB (gP), double combine,
// re-zeroes gAcc for the next graph replay.
__global__ __launch_bounds__(512) void club_final_kernel(float* __restrict__ out)
{
    __shared__ double sd[512];
    __shared__ double sp[512];
    const int tid = threadIdx.x;   // tid == feature d

    const double X  = (double)gAcc[0 * DD + tid];
    const double XX = (double)gAcc[1 * DD + tid];
    const double S  = (double)gAcc[2 * DD + tid];
    const double T  = (double)gAcc[3 * DD + tid];
    gAcc[0 * DD + tid] = 0.f;
    gAcc[1 * DD + tid] = 0.f;
    gAcc[2 * DD + tid] = 0.f;
    gAcc[3 * DD + tid] = 0.f;

    sd[tid] = XX * S - 2.0 * X * T;
    sp[tid] = (double)gP[tid] + (double)gP[tid + 512];
    __syncthreads();

    #pragma unroll
    for (int o = 256; o; o >>= 1) {
        if (tid < o) { sd[tid] += sd[tid + o]; sp[tid] += sp[tid + o]; }
        __syncthreads();
    }
    if (tid == 0) {
        const double N = (double)NTOK;
        out[0] = (float)((-0.5 * sp[0] + 0.5 * sd[0] / N) / N);
    }
}

extern "C" void kernel_launch(void* const* d_in, const int* in_sizes, int n_in,
                              void* d_out, int out_size)
{
    const float* x   = (const float*)d_in[0];
    const float* pmu = (const float*)d_in[1];
    const float* plv = (const float*)d_in[2];
    float* out = (float*)d_out;

    club_main_kernel<<<1024, 256>>>(x, pmu, plv);
    club_final_kernel<<<1, 512>>>(out);
}